// round 6
// baseline (speedup 1.0000x reference)
#include <cuda_runtime.h>
#include <cuda_bf16.h>
#include <stdint.h>
#include <math.h>

// ---------------------------------------------------------------------------
// Problem constants
// ---------------------------------------------------------------------------
#define BB   2
#define SS   1025
#define DD   1024
#define HH_  16
#define HD_  64
#define PP   1024
#define KR_  32
#define SCALE_ 0.125f
#define INV_TEMP 10.0f

// ---------------------------------------------------------------------------
// Scratch
// ---------------------------------------------------------------------------
static const size_t N_XN  = 2050ull * 1024;
static const size_t N_QR  = 2048ull * 1024;
static const size_t N_KR  = 2048ull * 1024;
static const size_t N_SC  = 2048ull * 1024;
static const size_t N_QKV = 2050ull * 3072;
static const size_t N_ATT = 2050ull * 1024;
static const size_t N_HH  = 2050ull * 4096;
static const size_t N_HN  = 2050ull * 1024;
static const size_t N_LW  = 2048ull * 32;
static const size_t N_RT  = 2048ull * 32;

static const size_t OFF_XN  = 0;
static const size_t OFF_QR  = OFF_XN  + N_XN;
static const size_t OFF_KR  = OFF_QR  + N_QR;
static const size_t OFF_SC  = OFF_KR  + N_KR;
static const size_t OFF_QKV = OFF_SC  + N_SC;
static const size_t OFF_ATT = OFF_QKV + N_QKV;
static const size_t OFF_HH  = OFF_ATT + N_ATT;
static const size_t OFF_HN  = OFF_HH  + N_HH;
static const size_t OFF_LW  = OFF_HN  + N_HN;
static const size_t OFF_RT  = OFF_LW  + N_LW;
static const size_t SCR_TOTAL = OFF_RT + N_RT;

__device__ float g_scratch[SCR_TOTAL];

// ---------------------------------------------------------------------------
// Block reductions (blockDim.x == 256)
// ---------------------------------------------------------------------------
__device__ __forceinline__ float blockReduceSum(float v, float* sbuf) {
    int lane = threadIdx.x & 31, wid = threadIdx.x >> 5;
    #pragma unroll
    for (int o = 16; o; o >>= 1) v += __shfl_xor_sync(0xffffffffu, v, o);
    if (lane == 0) sbuf[wid] = v;
    __syncthreads();
    if (wid == 0) {
        v = (lane < 8) ? sbuf[lane] : 0.f;
        #pragma unroll
        for (int o = 4; o; o >>= 1) v += __shfl_xor_sync(0xffffffffu, v, o);
        if (lane == 0) sbuf[0] = v;
    }
    __syncthreads();
    float r = sbuf[0];
    __syncthreads();
    return r;
}

__device__ __forceinline__ float blockReduceMax(float v, float* sbuf) {
    int lane = threadIdx.x & 31, wid = threadIdx.x >> 5;
    #pragma unroll
    for (int o = 16; o; o >>= 1) v = fmaxf(v, __shfl_xor_sync(0xffffffffu, v, o));
    if (lane == 0) sbuf[wid] = v;
    __syncthreads();
    if (wid == 0) {
        v = (lane < 8) ? sbuf[lane] : -3.4e38f;
        #pragma unroll
        for (int o = 4; o; o >>= 1) v = fmaxf(v, __shfl_xor_sync(0xffffffffu, v, o));
        if (lane == 0) sbuf[0] = v;
    }
    __syncthreads();
    float r = sbuf[0];
    __syncthreads();
    return r;
}

// ---------------------------------------------------------------------------
// LayerNorm
// ---------------------------------------------------------------------------
__global__ void layernorm_kernel(const float* __restrict__ in,
                                 const float* __restrict__ w,
                                 const float* __restrict__ b,
                                 float* __restrict__ out) {
    __shared__ float red[32];
    int row = blockIdx.x, tid = threadIdx.x;
    const float4* ip = (const float4*)(in + (size_t)row * 1024);
    float4 v = ip[tid];
    float s = v.x + v.y + v.z + v.w;
    float mean = blockReduceSum(s, red) * (1.f / 1024.f);
    float dx = v.x - mean, dy = v.y - mean, dz = v.z - mean, dw = v.w - mean;
    float ss = dx * dx + dy * dy + dz * dz + dw * dw;
    float var = blockReduceSum(ss, red) * (1.f / 1024.f);
    float rstd = rsqrtf(var + 1e-5f);
    float4 wv = ((const float4*)w)[tid];
    float4 bv = ((const float4*)b)[tid];
    float4 o;
    o.x = dx * rstd * wv.x + bv.x;
    o.y = dy * rstd * wv.y + bv.y;
    o.z = dz * rstd * wv.z + bv.z;
    o.w = dw * rstd * wv.w + bv.w;
    ((float4*)(out + (size_t)row * 1024))[tid] = o;
}

// ---------------------------------------------------------------------------
// L2 norm (in-place), rows of 1024
// ---------------------------------------------------------------------------
__global__ void l2norm_kernel(float* __restrict__ buf) {
    __shared__ float red[32];
    int row = blockIdx.x, tid = threadIdx.x;
    float4* p = (float4*)(buf + (size_t)row * 1024);
    float4 v = p[tid];
    float ss = v.x * v.x + v.y * v.y + v.z * v.z + v.w * v.w;
    float tot = blockReduceSum(ss, red);
    float sc = 1.f / fmaxf(sqrtf(tot), 1e-12f);
    v.x *= sc; v.y *= sc; v.z *= sc; v.w *= sc;
    p[tid] = v;
}

// ---------------------------------------------------------------------------
// 3xTF32 tensor-core NT GEMM: C[M,N] = A[M,K] * W[N,K]^T  (+ epilogue)
// 128x128 block tile, 256 threads, 8 warps of 32x64, BK=16, m16n8k8 tf32.
// Error-compensated: acc += lo_a*hi_b + hi_a*lo_b + hi_a*hi_b  (~fp32 accurate)
// ---------------------------------------------------------------------------
#define EPI_BIAS        1
#define EPI_BIAS_RESID  2
#define EPI_BIAS_GELU   3
#define EPI_SCORES      4

__device__ __forceinline__ unsigned f2tf32(float f) {
    unsigned u;
    asm("cvt.rna.tf32.f32 %0, %1;" : "=r"(u) : "f"(f));
    return u;
}

__device__ __forceinline__ void mma_tf32(float* d, const unsigned* a, const unsigned* b) {
    asm volatile(
        "mma.sync.aligned.m16n8k8.row.col.f32.tf32.tf32.f32 "
        "{%0,%1,%2,%3}, {%4,%5,%6,%7}, {%8,%9}, {%0,%1,%2,%3};"
        : "+f"(d[0]), "+f"(d[1]), "+f"(d[2]), "+f"(d[3])
        : "r"(a[0]), "r"(a[1]), "r"(a[2]), "r"(a[3]), "r"(b[0]), "r"(b[1]));
}

__device__ __forceinline__ void cpasync16(unsigned dst, const float* src, unsigned sz) {
    asm volatile("cp.async.ca.shared.global [%0], [%1], 16, %2;"
                 :: "r"(dst), "l"(src), "r"(sz));
}

__device__ __forceinline__ void split_tf32(float f, unsigned& hi, unsigned& lo) {
    hi = f2tf32(f);
    lo = f2tf32(f - __uint_as_float(hi));
}

#define SMSTRIDE 20   // 16 + 4 pad floats

template <int EPI>
__global__ __launch_bounds__(256) void gemm_tf32x3(
    const float* __restrict__ A, const float* __restrict__ W,
    const float* __restrict__ bias, const float* __restrict__ extra,
    float* __restrict__ C, int M, int N, int Kd,
    long sA, long sW, long sC) {

    A += (long)blockIdx.z * sA;
    W += (long)blockIdx.z * sW;
    C += (long)blockIdx.z * sC;

    __shared__ float As[2][128][SMSTRIDE];
    __shared__ float Bs[2][128][SMSTRIDE];

    const int tid  = threadIdx.x;
    const int lane = tid & 31;
    const int wid  = tid >> 5;
    const int wr   = wid & 3;          // 4 warp rows  -> 32 rows each
    const int wc   = wid >> 2;         // 2 warp cols  -> 64 cols each
    const int g    = lane >> 2;        // 0..7
    const int tig  = lane & 3;         // 0..3
    const int bm   = blockIdx.y * 128;
    const int bn   = blockIdx.x * 128;

    float acc[2][8][4];
    #pragma unroll
    for (int mi = 0; mi < 2; mi++)
        #pragma unroll
        for (int ni = 0; ni < 8; ni++)
            #pragma unroll
            for (int r = 0; r < 4; r++) acc[mi][ni][r] = 0.f;

    // global load mapping: 256 threads, each covers 2x16B of A row + 2x16B of B row
    const int ldRow  = tid >> 1;          // 0..127
    const int ldSide = tid & 1;           // 0/1 -> chunk pair
    const int aRow = bm + ldRow;
    const int aRowC = (aRow < M) ? aRow : (M - 1);
    const unsigned aSz = (aRow < M) ? 16u : 0u;
    const float* aBase = A + (long)aRowC * Kd + ldSide * 8;
    const float* bBase = W + (long)(bn + ldRow) * Kd + ldSide * 8;

    const unsigned daBase = (unsigned)__cvta_generic_to_shared(&As[0][ldRow][ldSide * 8]);
    const unsigned dbBase = (unsigned)__cvta_generic_to_shared(&Bs[0][ldRow][ldSide * 8]);
    const unsigned stageBytes = 128u * SMSTRIDE * 4u;

    const int nIter = Kd >> 4;

    #pragma unroll
    for (int c = 0; c < 2; c++) {
        cpasync16(daBase + c * 16, aBase + c * 4, aSz);
        cpasync16(dbBase + c * 16, bBase + c * 4, 16u);
    }
    asm volatile("cp.async.commit_group;");
    if (nIter > 1) {
        #pragma unroll
        for (int c = 0; c < 2; c++) {
            cpasync16(daBase + stageBytes + c * 16, aBase + 16 + c * 4, aSz);
            cpasync16(dbBase + stageBytes + c * 16, bBase + 16 + c * 4, 16u);
        }
        asm volatile("cp.async.commit_group;");
    }

    for (int it = 0; it < nIter; ++it) {
        if (it == nIter - 1) asm volatile("cp.async.wait_group 0;");
        else                 asm volatile("cp.async.wait_group 1;");
        __syncthreads();

        const int s = it & 1;
        #pragma unroll
        for (int ks = 0; ks < 2; ks++) {
            const int kb = ks * 8;
            unsigned Ah[2][4], Al[2][4];
            unsigned Bh[8][2], Bl[8][2];
            #pragma unroll
            for (int mi = 0; mi < 2; mi++) {
                const float* ap = &As[s][wr * 32 + mi * 16 + g][kb + tig];
                split_tf32(ap[0],                 Ah[mi][0], Al[mi][0]);
                split_tf32(ap[8 * SMSTRIDE],      Ah[mi][1], Al[mi][1]);
                split_tf32(ap[4],                 Ah[mi][2], Al[mi][2]);
                split_tf32(ap[8 * SMSTRIDE + 4],  Ah[mi][3], Al[mi][3]);
            }
            #pragma unroll
            for (int ni = 0; ni < 8; ni++) {
                const float* bp = &Bs[s][wc * 64 + ni * 8 + g][kb + tig];
                split_tf32(bp[0], Bh[ni][0], Bl[ni][0]);
                split_tf32(bp[4], Bh[ni][1], Bl[ni][1]);
            }
            #pragma unroll
            for (int mi = 0; mi < 2; mi++)
                #pragma unroll
                for (int ni = 0; ni < 8; ni++) {
                    mma_tf32(acc[mi][ni], Al[mi], Bh[ni]);
                    mma_tf32(acc[mi][ni], Ah[mi], Bl[ni]);
                    mma_tf32(acc[mi][ni], Ah[mi], Bh[ni]);
                }
        }
        __syncthreads();

        if (it + 2 < nIter) {
            const int k0 = (it + 2) * 16;
            const unsigned off = (unsigned)s * stageBytes;
            #pragma unroll
            for (int c = 0; c < 2; c++) {
                cpasync16(daBase + off + c * 16, aBase + k0 + c * 4, aSz);
                cpasync16(dbBase + off + c * 16, bBase + k0 + c * 4, 16u);
            }
            asm volatile("cp.async.commit_group;");
        }
    }

    // epilogue
    #pragma unroll
    for (int mi = 0; mi < 2; mi++) {
        #pragma unroll
        for (int rr = 0; rr < 2; rr++) {
            const int m = bm + wr * 32 + mi * 16 + g + rr * 8;
            if (m >= M) continue;
            #pragma unroll
            for (int ni = 0; ni < 8; ni++) {
                #pragma unroll
                for (int cc = 0; cc < 2; cc++) {
                    const int n = bn + wc * 64 + ni * 8 + tig * 2 + cc;
                    float v = acc[mi][ni][rr * 2 + cc];
                    if (EPI == EPI_BIAS) {
                        v += bias[n];
                    } else if (EPI == EPI_BIAS_RESID) {
                        v += bias[n] + extra[(long)m * N + n];
                    } else if (EPI == EPI_BIAS_GELU) {
                        v += bias[n];
                        v = 0.5f * v * (1.0f + erff(v * 0.70710678118654752f));
                    } else if (EPI == EPI_SCORES) {
                        v += extra[(long)m * N + n];
                        if (m == n) v = -1e9f;
                    }
                    C[(long)m * N + n] = v;
                }
            }
        }
    }
}

// ---------------------------------------------------------------------------
// Top-K=32 + log-softmax routing weights (clipped)
// ---------------------------------------------------------------------------
__global__ void topk_kernel(const float* __restrict__ scores,
                            int* __restrict__ routes,
                            float* __restrict__ logw) {
    __shared__ float s[1024];
    __shared__ float selv[32];
    __shared__ int   seli[32];
    __shared__ float rv[8];
    __shared__ int   ri[8];
    int row = blockIdx.x, tid = threadIdx.x;
    int lane = tid & 31, wid = tid >> 5;
    const float* src = scores + (size_t)row * 1024;
    s[tid] = src[tid]; s[tid + 256] = src[tid + 256];
    s[tid + 512] = src[tid + 512]; s[tid + 768] = src[tid + 768];
    __syncthreads();

    for (int it = 0; it < 32; it++) {
        float bv = -3.4e38f; int bi = 0x7fffffff;
        #pragma unroll
        for (int c = 0; c < 4; c++) {
            int idx = tid + c * 256;
            float v = s[idx];
            if (v > bv || (v == bv && idx < bi)) { bv = v; bi = idx; }
        }
        #pragma unroll
        for (int o = 16; o; o >>= 1) {
            float ov = __shfl_xor_sync(0xffffffffu, bv, o);
            int   oi = __shfl_xor_sync(0xffffffffu, bi, o);
            if (ov > bv || (ov == bv && oi < bi)) { bv = ov; bi = oi; }
        }
        if (lane == 0) { rv[wid] = bv; ri[wid] = bi; }
        __syncthreads();
        if (tid == 0) {
            float fv = rv[0]; int fi = ri[0];
            #pragma unroll
            for (int wn = 1; wn < 8; wn++)
                if (rv[wn] > fv || (rv[wn] == fv && ri[wn] < fi)) { fv = rv[wn]; fi = ri[wn]; }
            selv[it] = fv; seli[it] = fi;
            s[fi] = -3.4e38f;
        }
        __syncthreads();
    }

    if (tid < 32) {
        float t = selv[tid] * INV_TEMP;
        float tmax = selv[0] * INV_TEMP;
        float e = expf(t - tmax);
        float z = e;
        #pragma unroll
        for (int o = 16; o; o >>= 1) z += __shfl_xor_sync(0xffffffffu, z, o);
        float lw = t - (tmax + logf(z));
        routes[(size_t)row * 32 + tid] = seli[tid];
        logw[(size_t)row * 32 + tid] = fmaxf(lw, -10.f);
    }
}

// ---------------------------------------------------------------------------
// CLS attention
// ---------------------------------------------------------------------------
__global__ void cls_attn_kernel(const float* __restrict__ qkv,
                                float* __restrict__ attn) {
    __shared__ float q[64];
    __shared__ float sp[SS];
    __shared__ float red[32];
    __shared__ float po[4][64];
    int bh = blockIdx.x, b = bh >> 4, h = bh & 15;
    int tid = threadIdx.x;
    const float* base = qkv + (size_t)b * SS * 3072;
    if (tid < 64) q[tid] = base[h * 64 + tid];
    __syncthreads();

    float lmax = -3.4e38f;
    for (int j = tid; j < SS; j += 256) {
        const float* kr = base + (size_t)j * 3072 + 1024 + h * 64;
        float d = 0.f;
        #pragma unroll
        for (int dd = 0; dd < 64; dd++) d += q[dd] * kr[dd];
        d *= SCALE_;
        sp[j] = d;
        lmax = fmaxf(lmax, d);
    }
    float M = blockReduceMax(lmax, red);
    float ls = 0.f;
    for (int j = tid; j < SS; j += 256) {
        float e = expf(sp[j] - M);
        sp[j] = e;
        ls += e;
    }
    float Z = blockReduceSum(ls, red);

    int g = tid >> 6, d = tid & 63;
    float o = 0.f;
    for (int j = g; j < SS; j += 4)
        o += sp[j] * base[(size_t)j * 3072 + 2048 + h * 64 + d];
    po[g][d] = o;
    __syncthreads();
    if (tid < 64) {
        float r = (po[0][tid] + po[1][tid] + po[2][tid] + po[3][tid]) / Z;
        attn[(size_t)b * SS * 1024 + h * 64 + tid] = r;
    }
}

// ---------------------------------------------------------------------------
// Routed patch attention
// ---------------------------------------------------------------------------
__global__ void patch_attn_kernel(const float* __restrict__ qkv,
                                  const int* __restrict__ routes,
                                  const float* __restrict__ logw,
                                  float* __restrict__ attn) {
    __shared__ float Kg[32][64];
    __shared__ float Vg[32][64];
    __shared__ float q[64];
    __shared__ float sc[32];
    __shared__ int   rt[32];
    __shared__ float lw[32];
    __shared__ float po[4][64];
    int bp = blockIdx.x, b = bp >> 10, p = bp & 1023;
    int tid = threadIdx.x, lane = tid & 31, w = tid >> 5;
    if (tid < 32) {
        rt[tid] = routes[(size_t)bp * 32 + tid];
        lw[tid] = logw[(size_t)bp * 32 + tid];
    }
    __syncthreads();
    const float* base = qkv + (size_t)b * SS * 3072;
    const size_t qoff = (size_t)(p + 1) * 3072;

    for (int h = 0; h < HH_; h++) {
        if (tid < 64) q[tid] = base[qoff + h * 64 + tid];
        for (int e = tid; e < 2048; e += 256) {
            int k = e >> 6, d = e & 63;
            size_t toff = (size_t)(rt[k] + 1) * 3072 + h * 64 + d;
            Kg[k][d] = base[toff + 1024];
            Vg[k][d] = base[toff + 2048];
        }
        __syncthreads();

        for (int kk = w; kk < 32; kk += 8) {
            float part = q[lane] * Kg[kk][lane] + q[lane + 32] * Kg[kk][lane + 32];
            #pragma unroll
            for (int o = 16; o; o >>= 1) part += __shfl_xor_sync(0xffffffffu, part, o);
            if (lane == 0) sc[kk] = part * SCALE_ + lw[kk];
        }
        __syncthreads();

        if (tid < 32) {
            float v = sc[tid], m = v;
            #pragma unroll
            for (int o = 16; o; o >>= 1) m = fmaxf(m, __shfl_xor_sync(0xffffffffu, m, o));
            float e = expf(v - m), z = e;
            #pragma unroll
            for (int o = 16; o; o >>= 1) z += __shfl_xor_sync(0xffffffffu, z, o);
            sc[tid] = e / z;
        }
        __syncthreads();

        int g = tid >> 6, d = tid & 63;
        float o = 0.f;
        #pragma unroll
        for (int kk = g; kk < 32; kk += 4) o += sc[kk] * Vg[kk][d];
        po[g][d] = o;
        __syncthreads();
        if (tid < 64)
            attn[((size_t)b * SS + p + 1) * 1024 + h * 64 + tid] =
                po[0][tid] + po[1][tid] + po[2][tid] + po[3][tid];
        __syncthreads();
    }
}

// ---------------------------------------------------------------------------
// Orchestration
// ---------------------------------------------------------------------------
extern "C" void kernel_launch(void* const* d_in, const int* in_sizes, int n_in,
                              void* d_out, int out_size) {
    const float* x        = (const float*)d_in[0];
    const float* n1w      = (const float*)d_in[1];
    const float* n1b      = (const float*)d_in[2];
    const float* rq_w     = (const float*)d_in[3];
    const float* rq_b     = (const float*)d_in[4];
    const float* rk_w     = (const float*)d_in[5];
    const float* rk_b     = (const float*)d_in[6];
    const float* pos_bias = (const float*)d_in[7];
    const float* qkv_w    = (const float*)d_in[8];
    const float* qkv_b    = (const float*)d_in[9];
    const float* proj_w   = (const float*)d_in[10];
    const float* proj_b   = (const float*)d_in[11];
    const float* n2w      = (const float*)d_in[12];
    const float* n2b      = (const float*)d_in[13];
    const float* fc1_w    = (const float*)d_in[14];
    const float* fc1_b    = (const float*)d_in[15];
    const float* fc2_w    = (const float*)d_in[16];
    const float* fc2_b    = (const float*)d_in[17];
    float* out = (float*)d_out;

    void* sp = nullptr;
    cudaGetSymbolAddress(&sp, g_scratch);
    float* SCR = (float*)sp;
    float* XN  = SCR + OFF_XN;
    float* QR  = SCR + OFF_QR;
    float* KRb = SCR + OFF_KR;
    float* SC  = SCR + OFF_SC;
    float* QKV = SCR + OFF_QKV;
    float* ATT = SCR + OFF_ATT;
    float* HHp = SCR + OFF_HH;
    float* HN  = SCR + OFF_HN;
    float* LW  = SCR + OFF_LW;
    int*   RT  = (int*)(SCR + OFF_RT);

    // 1. LayerNorm 1
    layernorm_kernel<<<BB * SS, 256>>>(x, n1w, n1b, XN);

    // 2. Routing projections (per batch via z-stride)
    dim3 gR(8, 8, 2);
    gemm_tf32x3<EPI_BIAS><<<gR, 256>>>(XN + 1024, rq_w, rq_b, nullptr, QR,
                                       1024, 1024, 1024,
                                       (long)SS * DD, 0, (long)PP * DD);
    gemm_tf32x3<EPI_BIAS><<<gR, 256>>>(XN + 1024, rk_w, rk_b, nullptr, KRb,
                                       1024, 1024, 1024,
                                       (long)SS * DD, 0, (long)PP * DD);

    // 3. L2 normalize q_r and k_r
    l2norm_kernel<<<2 * BB * PP, 256>>>(QR);

    // 4. Routing scores
    gemm_tf32x3<EPI_SCORES><<<gR, 256>>>(QR, KRb, nullptr, pos_bias, SC,
                                         1024, 1024, 1024,
                                         (long)PP * DD, (long)PP * DD, (long)PP * PP);

    // 5. Top-32 + routing weights
    topk_kernel<<<BB * PP, 256>>>(SC, RT, LW);

    // 6. QKV projection
    dim3 gQ(24, 17, 1);
    gemm_tf32x3<EPI_BIAS><<<gQ, 256>>>(XN, qkv_w, qkv_b, nullptr, QKV,
                                       2050, 3072, 1024, 0, 0, 0);

    // 7. CLS attention
    cls_attn_kernel<<<BB * HH_, 256>>>(QKV, ATT);

    // 8. Routed patch attention
    patch_attn_kernel<<<BB * PP, 256>>>(QKV, RT, LW, ATT);

    // 9. Output projection + residual
    dim3 gP(8, 17, 1);
    gemm_tf32x3<EPI_BIAS_RESID><<<gP, 256>>>(ATT, proj_w, proj_b, x, out,
                                             2050, 1024, 1024, 0, 0, 0);

    // 10. LayerNorm 2
    layernorm_kernel<<<BB * SS, 256>>>(out, n2w, n2b, HN);

    // 11. FC1 + exact GELU
    dim3 gF1(32, 17, 1);
    gemm_tf32x3<EPI_BIAS_GELU><<<gF1, 256>>>(HN, fc1_w, fc1_b, nullptr, HHp,
                                             2050, 4096, 1024, 0, 0, 0);

    // 12. FC2 + residual
    dim3 gF2(8, 17, 1);
    gemm_tf32x3<EPI_BIAS_RESID><<<gF2, 256>>>(HHp, fc2_w, fc2_b, out, out,
                                              2050, 1024, 4096, 0, 0, 0);

    (void)in_sizes; (void)n_in; (void)out_size;
}

// round 8
// speedup vs baseline: 2.5136x; 2.5136x over previous
#include <cuda_runtime.h>
#include <cuda_bf16.h>
#include <stdint.h>
#include <math.h>

// ---------------------------------------------------------------------------
// Problem constants
// ---------------------------------------------------------------------------
#define BB   2
#define SS   1025
#define DD   1024
#define HH_  16
#define HD_  64
#define PP   1024
#define KR_  32
#define SCALE_ 0.125f
#define INV_TEMP 10.0f

// ---------------------------------------------------------------------------
// Scratch
// ---------------------------------------------------------------------------
static const size_t N_XN  = 2050ull * 1024;
static const size_t N_QR  = 2048ull * 1024;
static const size_t N_KR  = 2048ull * 1024;
static const size_t N_SC  = 2048ull * 1024;
static const size_t N_QKV = 2050ull * 3072;
static const size_t N_ATT = 2050ull * 1024;
static const size_t N_HH  = 2050ull * 4096;
static const size_t N_HN  = 2050ull * 1024;
static const size_t N_LW  = 2048ull * 32;
static const size_t N_RT  = 2048ull * 32;

static const size_t OFF_XN  = 0;
static const size_t OFF_QR  = OFF_XN  + N_XN;
static const size_t OFF_KR  = OFF_QR  + N_QR;
static const size_t OFF_SC  = OFF_KR  + N_KR;
static const size_t OFF_QKV = OFF_SC  + N_SC;
static const size_t OFF_ATT = OFF_QKV + N_QKV;
static const size_t OFF_HH  = OFF_ATT + N_ATT;
static const size_t OFF_HN  = OFF_HH  + N_HH;
static const size_t OFF_LW  = OFF_HN  + N_HN;
static const size_t OFF_RT  = OFF_LW  + N_LW;
static const size_t SCR_TOTAL = OFF_RT + N_RT;

__device__ float g_scratch[SCR_TOTAL];

// ---------------------------------------------------------------------------
// Block reductions (blockDim.x == 256)
// ---------------------------------------------------------------------------
__device__ __forceinline__ float blockReduceSum(float v, float* sbuf) {
    int lane = threadIdx.x & 31, wid = threadIdx.x >> 5;
    #pragma unroll
    for (int o = 16; o; o >>= 1) v += __shfl_xor_sync(0xffffffffu, v, o);
    if (lane == 0) sbuf[wid] = v;
    __syncthreads();
    if (wid == 0) {
        v = (lane < 8) ? sbuf[lane] : 0.f;
        #pragma unroll
        for (int o = 4; o; o >>= 1) v += __shfl_xor_sync(0xffffffffu, v, o);
        if (lane == 0) sbuf[0] = v;
    }
    __syncthreads();
    float r = sbuf[0];
    __syncthreads();
    return r;
}

__device__ __forceinline__ float blockReduceMax(float v, float* sbuf) {
    int lane = threadIdx.x & 31, wid = threadIdx.x >> 5;
    #pragma unroll
    for (int o = 16; o; o >>= 1) v = fmaxf(v, __shfl_xor_sync(0xffffffffu, v, o));
    if (lane == 0) sbuf[wid] = v;
    __syncthreads();
    if (wid == 0) {
        v = (lane < 8) ? sbuf[lane] : -3.4e38f;
        #pragma unroll
        for (int o = 4; o; o >>= 1) v = fmaxf(v, __shfl_xor_sync(0xffffffffu, v, o));
        if (lane == 0) sbuf[0] = v;
    }
    __syncthreads();
    float r = sbuf[0];
    __syncthreads();
    return r;
}

// ---------------------------------------------------------------------------
// LayerNorm
// ---------------------------------------------------------------------------
__global__ void layernorm_kernel(const float* __restrict__ in,
                                 const float* __restrict__ w,
                                 const float* __restrict__ b,
                                 float* __restrict__ out) {
    __shared__ float red[32];
    int row = blockIdx.x, tid = threadIdx.x;
    const float4* ip = (const float4*)(in + (size_t)row * 1024);
    float4 v = ip[tid];
    float s = v.x + v.y + v.z + v.w;
    float mean = blockReduceSum(s, red) * (1.f / 1024.f);
    float dx = v.x - mean, dy = v.y - mean, dz = v.z - mean, dw = v.w - mean;
    float ss = dx * dx + dy * dy + dz * dz + dw * dw;
    float var = blockReduceSum(ss, red) * (1.f / 1024.f);
    float rstd = rsqrtf(var + 1e-5f);
    float4 wv = ((const float4*)w)[tid];
    float4 bv = ((const float4*)b)[tid];
    float4 o;
    o.x = dx * rstd * wv.x + bv.x;
    o.y = dy * rstd * wv.y + bv.y;
    o.z = dz * rstd * wv.z + bv.z;
    o.w = dw * rstd * wv.w + bv.w;
    ((float4*)(out + (size_t)row * 1024))[tid] = o;
}

// ---------------------------------------------------------------------------
// L2 norm (in-place), rows of 1024
// ---------------------------------------------------------------------------
__global__ void l2norm_kernel(float* __restrict__ buf) {
    __shared__ float red[32];
    int row = blockIdx.x, tid = threadIdx.x;
    float4* p = (float4*)(buf + (size_t)row * 1024);
    float4 v = p[tid];
    float ss = v.x * v.x + v.y * v.y + v.z * v.z + v.w * v.w;
    float tot = blockReduceSum(ss, red);
    float sc = 1.f / fmaxf(sqrtf(tot), 1e-12f);
    v.x *= sc; v.y *= sc; v.z *= sc; v.w *= sc;
    p[tid] = v;
}

// ---------------------------------------------------------------------------
// bf16x3 tensor-core NT GEMM: C[M,N] = A[M,K] * W[N,K]^T  (+ epilogue)
// a*b ~= ah*bh + al*bh + ah*bl, split once at smem fill.
// 128x128 block tile, 256 threads, 8 warps of 32x64, chunk=32 k, m16n8k16.
// Dynamic smem: hi/lo bf16 tiles for A and B, double buffered (80 KB).
// ---------------------------------------------------------------------------
#define EPI_BIAS        1
#define EPI_BIAS_RESID  2
#define EPI_BIAS_GELU   3
#define EPI_SCORES      4

#define KSTRIDE 40                      // 32 + 8 pad, bf16 units
#define TILE_BF16 (128 * KSTRIDE)       // one (stage,hl) plane
#define SMA(st,hl,row,k) ((((st) * 2 + (hl)) * 128 + (row)) * KSTRIDE + (k))
#define SB_BASE (4 * TILE_BF16)
#define GEMM_SMEM_BYTES (8 * TILE_BF16 * 2)   // 81920

__device__ __forceinline__ void mma_bf16(float* d, const unsigned* a, const unsigned* b) {
    asm volatile(
        "mma.sync.aligned.m16n8k16.row.col.f32.bf16.bf16.f32 "
        "{%0,%1,%2,%3}, {%4,%5,%6,%7}, {%8,%9}, {%0,%1,%2,%3};"
        : "+f"(d[0]), "+f"(d[1]), "+f"(d[2]), "+f"(d[3])
        : "r"(a[0]), "r"(a[1]), "r"(a[2]), "r"(a[3]), "r"(b[0]), "r"(b[1]));
}

__device__ __forceinline__ void cvt_store(__nv_bfloat16* sm, int hiIdx, int loIdx, float4 f) {
    __nv_bfloat162 h0 = __floats2bfloat162_rn(f.x, f.y);
    __nv_bfloat162 h1 = __floats2bfloat162_rn(f.z, f.w);
    float rx = f.x - __bfloat162float(h0.x);
    float ry = f.y - __bfloat162float(h0.y);
    float rz = f.z - __bfloat162float(h1.x);
    float rw = f.w - __bfloat162float(h1.y);
    __nv_bfloat162 l0 = __floats2bfloat162_rn(rx, ry);
    __nv_bfloat162 l1 = __floats2bfloat162_rn(rz, rw);
    uint2 hv, lv;
    hv.x = *(unsigned*)&h0; hv.y = *(unsigned*)&h1;
    lv.x = *(unsigned*)&l0; lv.y = *(unsigned*)&l1;
    *(uint2*)(sm + hiIdx) = hv;
    *(uint2*)(sm + loIdx) = lv;
}

template <int EPI>
__global__ __launch_bounds__(256) void gemm_bf16x3(
    const float* __restrict__ A, const float* __restrict__ W,
    const float* __restrict__ bias, const float* __restrict__ extra,
    float* __restrict__ C, int M, int N, int Kd,
    long sA, long sW, long sC) {

    A += (long)blockIdx.z * sA;
    W += (long)blockIdx.z * sW;
    C += (long)blockIdx.z * sC;

    extern __shared__ __nv_bfloat16 sm[];

    const int tid  = threadIdx.x;
    const int lane = tid & 31;
    const int wid  = tid >> 5;
    const int wr   = wid & 3;          // 4 warp rows -> 32 rows each
    const int wc   = wid >> 2;         // 2 warp cols -> 64 cols each
    const int g    = lane >> 2;
    const int tig  = lane & 3;
    const int bm   = blockIdx.y * 128;
    const int bn   = blockIdx.x * 128;

    float acc[2][8][4];
    #pragma unroll
    for (int mi = 0; mi < 2; mi++)
        #pragma unroll
        for (int ni = 0; ni < 8; ni++)
            #pragma unroll
            for (int r = 0; r < 4; r++) acc[mi][ni][r] = 0.f;

    // loader mapping: 256 threads -> 128 rows x 2 halves; each thread 4 float4
    const int ldRow  = tid >> 1;
    const int f4base = (tid & 1) * 4;
    const int aRow   = bm + ldRow;
    const int aRowC  = (aRow < M) ? aRow : (M - 1);
    const float* aBase = A + (long)aRowC * Kd;
    const float* bBase = W + (long)(bn + ldRow) * Kd;

    const int nIter = Kd >> 5;         // 32-k chunks
    float4 fa[4], fb[4];

    // prologue: load + convert/store stage 0
    {
        const float4* ap = (const float4*)aBase;
        const float4* bp = (const float4*)bBase;
        #pragma unroll
        for (int c = 0; c < 4; c++) { fa[c] = ap[f4base + c]; fb[c] = bp[f4base + c]; }
        #pragma unroll
        for (int c = 0; c < 4; c++) {
            int kp = (f4base + c) * 4;
            cvt_store(sm, SMA(0, 0, ldRow, kp), SMA(0, 1, ldRow, kp), fa[c]);
            cvt_store(sm, SB_BASE + SMA(0, 0, ldRow, kp), SB_BASE + SMA(0, 1, ldRow, kp), fb[c]);
        }
    }

    for (int it = 0; it < nIter; ++it) {
        const int s = it & 1;
        __syncthreads();   // stage s writes visible; stage 1-s reads (iter it-1) done

        if (it + 1 < nIter) {
            const float4* ap = (const float4*)(aBase + (it + 1) * 32);
            const float4* bp = (const float4*)(bBase + (it + 1) * 32);
            #pragma unroll
            for (int c = 0; c < 4; c++) { fa[c] = ap[f4base + c]; fb[c] = bp[f4base + c]; }
        }

        #pragma unroll
        for (int ks = 0; ks < 2; ks++) {
            const int kb = ks * 16;
            unsigned Ah[2][4], Al[2][4], Bh[8][2], Bl[8][2];
            #pragma unroll
            for (int mi = 0; mi < 2; mi++) {
                const int r0 = wr * 32 + mi * 16 + g;
                const int kc = kb + tig * 2;
                Ah[mi][0] = *(const unsigned*)&sm[SMA(s, 0, r0,     kc)];
                Ah[mi][1] = *(const unsigned*)&sm[SMA(s, 0, r0 + 8, kc)];
                Ah[mi][2] = *(const unsigned*)&sm[SMA(s, 0, r0,     kc + 8)];
                Ah[mi][3] = *(const unsigned*)&sm[SMA(s, 0, r0 + 8, kc + 8)];
                Al[mi][0] = *(const unsigned*)&sm[SMA(s, 1, r0,     kc)];
                Al[mi][1] = *(const unsigned*)&sm[SMA(s, 1, r0 + 8, kc)];
                Al[mi][2] = *(const unsigned*)&sm[SMA(s, 1, r0,     kc + 8)];
                Al[mi][3] = *(const unsigned*)&sm[SMA(s, 1, r0 + 8, kc + 8)];
            }
            #pragma unroll
            for (int ni = 0; ni < 8; ni++) {
                const int rn = wc * 64 + ni * 8 + g;
                const int kc = kb + tig * 2;
                Bh[ni][0] = *(const unsigned*)&sm[SB_BASE + SMA(s, 0, rn, kc)];
                Bh[ni][1] = *(const unsigned*)&sm[SB_BASE + SMA(s, 0, rn, kc + 8)];
                Bl[ni][0] = *(const unsigned*)&sm[SB_BASE + SMA(s, 1, rn, kc)];
                Bl[ni][1] = *(const unsigned*)&sm[SB_BASE + SMA(s, 1, rn, kc + 8)];
            }
            #pragma unroll
            for (int mi = 0; mi < 2; mi++)
                #pragma unroll
                for (int ni = 0; ni < 8; ni++) {
                    mma_bf16(acc[mi][ni], Ah[mi], Bh[ni]);
                    mma_bf16(acc[mi][ni], Al[mi], Bh[ni]);
                    mma_bf16(acc[mi][ni], Ah[mi], Bl[ni]);
                }
        }

        if (it + 1 < nIter) {
            const int sn = 1 - s;
            #pragma unroll
            for (int c = 0; c < 4; c++) {
                int kp = (f4base + c) * 4;
                cvt_store(sm, SMA(sn, 0, ldRow, kp), SMA(sn, 1, ldRow, kp), fa[c]);
                cvt_store(sm, SB_BASE + SMA(sn, 0, ldRow, kp), SB_BASE + SMA(sn, 1, ldRow, kp), fb[c]);
            }
        }
    }

    // epilogue
    #pragma unroll
    for (int mi = 0; mi < 2; mi++) {
        #pragma unroll
        for (int rr = 0; rr < 2; rr++) {
            const int m = bm + wr * 32 + mi * 16 + g + rr * 8;
            if (m >= M) continue;
            #pragma unroll
            for (int ni = 0; ni < 8; ni++) {
                #pragma unroll
                for (int cc = 0; cc < 2; cc++) {
                    const int n = bn + wc * 64 + ni * 8 + tig * 2 + cc;
                    float v = acc[mi][ni][rr * 2 + cc];
                    if (EPI == EPI_BIAS) {
                        v += bias[n];
                    } else if (EPI == EPI_BIAS_RESID) {
                        v += bias[n] + extra[(long)m * N + n];
                    } else if (EPI == EPI_BIAS_GELU) {
                        v += bias[n];
                        v = 0.5f * v * (1.0f + erff(v * 0.70710678118654752f));
                    } else if (EPI == EPI_SCORES) {
                        v += extra[(long)m * N + n];
                        if (m == n) v = -1e9f;
                    }
                    C[(long)m * N + n] = v;
                }
            }
        }
    }
}

// ---------------------------------------------------------------------------
// Top-K=32 + log-softmax routing weights (clipped)
// ---------------------------------------------------------------------------
__global__ void topk_kernel(const float* __restrict__ scores,
                            int* __restrict__ routes,
                            float* __restrict__ logw) {
    __shared__ float s[1024];
    __shared__ float selv[32];
    __shared__ int   seli[32];
    __shared__ float rv[8];
    __shared__ int   ri[8];
    int row = blockIdx.x, tid = threadIdx.x;
    int lane = tid & 31, wid = tid >> 5;
    const float* src = scores + (size_t)row * 1024;
    s[tid] = src[tid]; s[tid + 256] = src[tid + 256];
    s[tid + 512] = src[tid + 512]; s[tid + 768] = src[tid + 768];
    __syncthreads();

    for (int it = 0; it < 32; it++) {
        float bv = -3.4e38f; int bi = 0x7fffffff;
        #pragma unroll
        for (int c = 0; c < 4; c++) {
            int idx = tid + c * 256;
            float v = s[idx];
            if (v > bv || (v == bv && idx < bi)) { bv = v; bi = idx; }
        }
        #pragma unroll
        for (int o = 16; o; o >>= 1) {
            float ov = __shfl_xor_sync(0xffffffffu, bv, o);
            int   oi = __shfl_xor_sync(0xffffffffu, bi, o);
            if (ov > bv || (ov == bv && oi < bi)) { bv = ov; bi = oi; }
        }
        if (lane == 0) { rv[wid] = bv; ri[wid] = bi; }
        __syncthreads();
        if (tid == 0) {
            float fv = rv[0]; int fi = ri[0];
            #pragma unroll
            for (int wn = 1; wn < 8; wn++)
                if (rv[wn] > fv || (rv[wn] == fv && ri[wn] < fi)) { fv = rv[wn]; fi = ri[wn]; }
            selv[it] = fv; seli[it] = fi;
            s[fi] = -3.4e38f;
        }
        __syncthreads();
    }

    if (tid < 32) {
        float t = selv[tid] * INV_TEMP;
        float tmax = selv[0] * INV_TEMP;
        float e = expf(t - tmax);
        float z = e;
        #pragma unroll
        for (int o = 16; o; o >>= 1) z += __shfl_xor_sync(0xffffffffu, z, o);
        float lw = t - (tmax + logf(z));
        routes[(size_t)row * 32 + tid] = seli[tid];
        logw[(size_t)row * 32 + tid] = fmaxf(lw, -10.f);
    }
}

// ---------------------------------------------------------------------------
// CLS attention
// ---------------------------------------------------------------------------
__global__ void cls_attn_kernel(const float* __restrict__ qkv,
                                float* __restrict__ attn) {
    __shared__ float q[64];
    __shared__ float sp[SS];
    __shared__ float red[32];
    __shared__ float po[4][64];
    int bh = blockIdx.x, b = bh >> 4, h = bh & 15;
    int tid = threadIdx.x;
    const float* base = qkv + (size_t)b * SS * 3072;
    if (tid < 64) q[tid] = base[h * 64 + tid];
    __syncthreads();

    float lmax = -3.4e38f;
    for (int j = tid; j < SS; j += 256) {
        const float* kr = base + (size_t)j * 3072 + 1024 + h * 64;
        float d = 0.f;
        #pragma unroll
        for (int dd = 0; dd < 64; dd++) d += q[dd] * kr[dd];
        d *= SCALE_;
        sp[j] = d;
        lmax = fmaxf(lmax, d);
    }
    float M = blockReduceMax(lmax, red);
    float ls = 0.f;
    for (int j = tid; j < SS; j += 256) {
        float e = expf(sp[j] - M);
        sp[j] = e;
        ls += e;
    }
    float Z = blockReduceSum(ls, red);

    int g = tid >> 6, d = tid & 63;
    float o = 0.f;
    for (int j = g; j < SS; j += 4)
        o += sp[j] * base[(size_t)j * 3072 + 2048 + h * 64 + d];
    po[g][d] = o;
    __syncthreads();
    if (tid < 64) {
        float r = (po[0][tid] + po[1][tid] + po[2][tid] + po[3][tid]) / Z;
        attn[(size_t)b * SS * 1024 + h * 64 + tid] = r;
    }
}

// ---------------------------------------------------------------------------
// Routed patch attention
// ---------------------------------------------------------------------------
__global__ void patch_attn_kernel(const float* __restrict__ qkv,
                                  const int* __restrict__ routes,
                                  const float* __restrict__ logw,
                                  float* __restrict__ attn) {
    __shared__ float Kg[32][64];
    __shared__ float Vg[32][64];
    __shared__ float q[64];
    __shared__ float sc[32];
    __shared__ int   rt[32];
    __shared__ float lw[32];
    __shared__ float po[4][64];
    int bp = blockIdx.x, b = bp >> 10, p = bp & 1023;
    int tid = threadIdx.x, lane = tid & 31, w = tid >> 5;
    if (tid < 32) {
        rt[tid] = routes[(size_t)bp * 32 + tid];
        lw[tid] = logw[(size_t)bp * 32 + tid];
    }
    __syncthreads();
    const float* base = qkv + (size_t)b * SS * 3072;
    const size_t qoff = (size_t)(p + 1) * 3072;

    for (int h = 0; h < HH_; h++) {
        if (tid < 64) q[tid] = base[qoff + h * 64 + tid];
        for (int e = tid; e < 2048; e += 256) {
            int k = e >> 6, d = e & 63;
            size_t toff = (size_t)(rt[k] + 1) * 3072 + h * 64 + d;
            Kg[k][d] = base[toff + 1024];
            Vg[k][d] = base[toff + 2048];
        }
        __syncthreads();

        for (int kk = w; kk < 32; kk += 8) {
            float part = q[lane] * Kg[kk][lane] + q[lane + 32] * Kg[kk][lane + 32];
            #pragma unroll
            for (int o = 16; o; o >>= 1) part += __shfl_xor_sync(0xffffffffu, part, o);
            if (lane == 0) sc[kk] = part * SCALE_ + lw[kk];
        }
        __syncthreads();

        if (tid < 32) {
            float v = sc[tid], m = v;
            #pragma unroll
            for (int o = 16; o; o >>= 1) m = fmaxf(m, __shfl_xor_sync(0xffffffffu, m, o));
            float e = expf(v - m), z = e;
            #pragma unroll
            for (int o = 16; o; o >>= 1) z += __shfl_xor_sync(0xffffffffu, z, o);
            sc[tid] = e / z;
        }
        __syncthreads();

        int g = tid >> 6, d = tid & 63;
        float o = 0.f;
        #pragma unroll
        for (int kk = g; kk < 32; kk += 4) o += sc[kk] * Vg[kk][d];
        po[g][d] = o;
        __syncthreads();
        if (tid < 64)
            attn[((size_t)b * SS + p + 1) * 1024 + h * 64 + tid] =
                po[0][tid] + po[1][tid] + po[2][tid] + po[3][tid];
        __syncthreads();
    }
}

// ---------------------------------------------------------------------------
// Orchestration
// ---------------------------------------------------------------------------
extern "C" void kernel_launch(void* const* d_in, const int* in_sizes, int n_in,
                              void* d_out, int out_size) {
    const float* x        = (const float*)d_in[0];
    const float* n1w      = (const float*)d_in[1];
    const float* n1b      = (const float*)d_in[2];
    const float* rq_w     = (const float*)d_in[3];
    const float* rq_b     = (const float*)d_in[4];
    const float* rk_w     = (const float*)d_in[5];
    const float* rk_b     = (const float*)d_in[6];
    const float* pos_bias = (const float*)d_in[7];
    const float* qkv_w    = (const float*)d_in[8];
    const float* qkv_b    = (const float*)d_in[9];
    const float* proj_w   = (const float*)d_in[10];
    const float* proj_b   = (const float*)d_in[11];
    const float* n2w      = (const float*)d_in[12];
    const float* n2b      = (const float*)d_in[13];
    const float* fc1_w    = (const float*)d_in[14];
    const float* fc1_b    = (const float*)d_in[15];
    const float* fc2_w    = (const float*)d_in[16];
    const float* fc2_b    = (const float*)d_in[17];
    float* out = (float*)d_out;

    void* sp = nullptr;
    cudaGetSymbolAddress(&sp, g_scratch);
    float* SCR = (float*)sp;
    float* XN  = SCR + OFF_XN;
    float* QR  = SCR + OFF_QR;
    float* KRb = SCR + OFF_KR;
    float* SC  = SCR + OFF_SC;
    float* QKV = SCR + OFF_QKV;
    float* ATT = SCR + OFF_ATT;
    float* HHp = SCR + OFF_HH;
    float* HN  = SCR + OFF_HN;
    float* LW  = SCR + OFF_LW;
    int*   RT  = (int*)(SCR + OFF_RT);

    // allow 80KB dynamic smem for the GEMM template instantiations (idempotent)
    cudaFuncSetAttribute(gemm_bf16x3<EPI_BIAS>,
                         cudaFuncAttributeMaxDynamicSharedMemorySize, GEMM_SMEM_BYTES);
    cudaFuncSetAttribute(gemm_bf16x3<EPI_BIAS_RESID>,
                         cudaFuncAttributeMaxDynamicSharedMemorySize, GEMM_SMEM_BYTES);
    cudaFuncSetAttribute(gemm_bf16x3<EPI_BIAS_GELU>,
                         cudaFuncAttributeMaxDynamicSharedMemorySize, GEMM_SMEM_BYTES);
    cudaFuncSetAttribute(gemm_bf16x3<EPI_SCORES>,
                         cudaFuncAttributeMaxDynamicSharedMemorySize, GEMM_SMEM_BYTES);

    // 1. LayerNorm 1
    layernorm_kernel<<<BB * SS, 256>>>(x, n1w, n1b, XN);

    // 2. Routing projections (per batch via z-stride)
    dim3 gR(8, 8, 2);
    gemm_bf16x3<EPI_BIAS><<<gR, 256, GEMM_SMEM_BYTES>>>(
        XN + 1024, rq_w, rq_b, nullptr, QR,
        1024, 1024, 1024, (long)SS * DD, 0, (long)PP * DD);
    gemm_bf16x3<EPI_BIAS><<<gR, 256, GEMM_SMEM_BYTES>>>(
        XN + 1024, rk_w, rk_b, nullptr, KRb,
        1024, 1024, 1024, (long)SS * DD, 0, (long)PP * DD);

    // 3. L2 normalize q_r and k_r
    l2norm_kernel<<<2 * BB * PP, 256>>>(QR);

    // 4. Routing scores
    gemm_bf16x3<EPI_SCORES><<<gR, 256, GEMM_SMEM_BYTES>>>(
        QR, KRb, nullptr, pos_bias, SC,
        1024, 1024, 1024, (long)PP * DD, (long)PP * DD, (long)PP * PP);

    // 5. Top-32 + routing weights
    topk_kernel<<<BB * PP, 256>>>(SC, RT, LW);

    // 6. QKV projection
    dim3 gQ(24, 17, 1);
    gemm_bf16x3<EPI_BIAS><<<gQ, 256, GEMM_SMEM_BYTES>>>(
        XN, qkv_w, qkv_b, nullptr, QKV, 2050, 3072, 1024, 0, 0, 0);

    // 7. CLS attention
    cls_attn_kernel<<<BB * HH_, 256>>>(QKV, ATT);

    // 8. Routed patch attention
    patch_attn_kernel<<<BB * PP, 256>>>(QKV, RT, LW, ATT);

    // 9. Output projection + residual
    dim3 gP(8, 17, 1);
    gemm_bf16x3<EPI_BIAS_RESID><<<gP, 256, GEMM_SMEM_BYTES>>>(
        ATT, proj_w, proj_b, x, out, 2050, 1024, 1024, 0, 0, 0);

    // 10. LayerNorm 2
    layernorm_kernel<<<BB * SS, 256>>>(out, n2w, n2b, HN);

    // 11. FC1 + exact GELU
    dim3 gF1(32, 17, 1);
    gemm_bf16x3<EPI_BIAS_GELU><<<gF1, 256, GEMM_SMEM_BYTES>>>(
        HN, fc1_w, fc1_b, nullptr, HHp, 2050, 4096, 1024, 0, 0, 0);

    // 12. FC2 + residual
    dim3 gF2(8, 17, 1);
    gemm_bf16x3<EPI_BIAS_RESID><<<gF2, 256, GEMM_SMEM_BYTES>>>(
        HHp, fc2_w, fc2_b, out, out, 2050, 1024, 4096, 0, 0, 0);

    (void)in_sizes; (void)n_in; (void)out_size;
}

// round 9
// speedup vs baseline: 2.8182x; 1.1212x over previous
#include <cuda_runtime.h>
#include <cuda_bf16.h>
#include <stdint.h>
#include <math.h>

// ---------------------------------------------------------------------------
// Problem constants
// ---------------------------------------------------------------------------
#define BB   2
#define SS   1025
#define DD   1024
#define HH_  16
#define HD_  64
#define PP   1024
#define KR_  32
#define SCALE_ 0.125f
#define INV_TEMP 10.0f

// ---------------------------------------------------------------------------
// Scratch
// ---------------------------------------------------------------------------
static const size_t N_XN  = 2050ull * 1024;
static const size_t N_QR  = 2048ull * 1024;
static const size_t N_KR  = 2048ull * 1024;
static const size_t N_SC  = 2048ull * 1024;
static const size_t N_QKV = 2050ull * 3072;
static const size_t N_ATT = 2050ull * 1024;
static const size_t N_HH  = 2050ull * 4096;
static const size_t N_HN  = 2050ull * 1024;
static const size_t N_LW  = 2048ull * 32;
static const size_t N_RT  = 2048ull * 32;

static const size_t OFF_XN  = 0;
static const size_t OFF_QR  = OFF_XN  + N_XN;
static const size_t OFF_KR  = OFF_QR  + N_QR;
static const size_t OFF_SC  = OFF_KR  + N_KR;
static const size_t OFF_QKV = OFF_SC  + N_SC;
static const size_t OFF_ATT = OFF_QKV + N_QKV;
static const size_t OFF_HH  = OFF_ATT + N_ATT;
static const size_t OFF_HN  = OFF_HH  + N_HH;
static const size_t OFF_LW  = OFF_HN  + N_HN;
static const size_t OFF_RT  = OFF_LW  + N_LW;
static const size_t SCR_TOTAL = OFF_RT + N_RT;

__device__ float g_scratch[SCR_TOTAL];

// ---------------------------------------------------------------------------
// Block reductions (blockDim.x == 256)
// ---------------------------------------------------------------------------
__device__ __forceinline__ float blockReduceSum(float v, float* sbuf) {
    int lane = threadIdx.x & 31, wid = threadIdx.x >> 5;
    #pragma unroll
    for (int o = 16; o; o >>= 1) v += __shfl_xor_sync(0xffffffffu, v, o);
    if (lane == 0) sbuf[wid] = v;
    __syncthreads();
    if (wid == 0) {
        v = (lane < 8) ? sbuf[lane] : 0.f;
        #pragma unroll
        for (int o = 4; o; o >>= 1) v += __shfl_xor_sync(0xffffffffu, v, o);
        if (lane == 0) sbuf[0] = v;
    }
    __syncthreads();
    float r = sbuf[0];
    __syncthreads();
    return r;
}

__device__ __forceinline__ float blockReduceMax(float v, float* sbuf) {
    int lane = threadIdx.x & 31, wid = threadIdx.x >> 5;
    #pragma unroll
    for (int o = 16; o; o >>= 1) v = fmaxf(v, __shfl_xor_sync(0xffffffffu, v, o));
    if (lane == 0) sbuf[wid] = v;
    __syncthreads();
    if (wid == 0) {
        v = (lane < 8) ? sbuf[lane] : -3.4e38f;
        #pragma unroll
        for (int o = 4; o; o >>= 1) v = fmaxf(v, __shfl_xor_sync(0xffffffffu, v, o));
        if (lane == 0) sbuf[0] = v;
    }
    __syncthreads();
    float r = sbuf[0];
    __syncthreads();
    return r;
}

// ---------------------------------------------------------------------------
// LayerNorm
// ---------------------------------------------------------------------------
__global__ void layernorm_kernel(const float* __restrict__ in,
                                 const float* __restrict__ w,
                                 const float* __restrict__ b,
                                 float* __restrict__ out) {
    __shared__ float red[32];
    int row = blockIdx.x, tid = threadIdx.x;
    const float4* ip = (const float4*)(in + (size_t)row * 1024);
    float4 v = ip[tid];
    float s = v.x + v.y + v.z + v.w;
    float mean = blockReduceSum(s, red) * (1.f / 1024.f);
    float dx = v.x - mean, dy = v.y - mean, dz = v.z - mean, dw = v.w - mean;
    float ss = dx * dx + dy * dy + dz * dz + dw * dw;
    float var = blockReduceSum(ss, red) * (1.f / 1024.f);
    float rstd = rsqrtf(var + 1e-5f);
    float4 wv = ((const float4*)w)[tid];
    float4 bv = ((const float4*)b)[tid];
    float4 o;
    o.x = dx * rstd * wv.x + bv.x;
    o.y = dy * rstd * wv.y + bv.y;
    o.z = dz * rstd * wv.z + bv.z;
    o.w = dw * rstd * wv.w + bv.w;
    ((float4*)(out + (size_t)row * 1024))[tid] = o;
}

// ---------------------------------------------------------------------------
// L2 norm (in-place), rows of 1024
// ---------------------------------------------------------------------------
__global__ void l2norm_kernel(float* __restrict__ buf) {
    __shared__ float red[32];
    int row = blockIdx.x, tid = threadIdx.x;
    float4* p = (float4*)(buf + (size_t)row * 1024);
    float4 v = p[tid];
    float ss = v.x * v.x + v.y * v.y + v.z * v.z + v.w * v.w;
    float tot = blockReduceSum(ss, red);
    float sc = 1.f / fmaxf(sqrtf(tot), 1e-12f);
    v.x *= sc; v.y *= sc; v.z *= sc; v.w *= sc;
    p[tid] = v;
}

// ---------------------------------------------------------------------------
// bf16x3 tensor-core NT GEMM with ldmatrix fragment loads.
// C[M,N] = A[M,K] * W[N,K]^T  (+ epilogue)
// a*b ~= ah*bh + al*bh + ah*bl, split once at smem fill.
// 128x128 block tile, 256 threads, 8 warps of 32x64, chunk=32 k, m16n8k16.
// ---------------------------------------------------------------------------
#define EPI_BIAS        1
#define EPI_BIAS_RESID  2
#define EPI_BIAS_GELU   3
#define EPI_SCORES      4

#define KSTRIDE 40                      // 32 + 8 pad, bf16 units
#define TILE_BF16 (128 * KSTRIDE)       // one (stage,hl) plane
#define SMA(st,hl,row,k) ((((st) * 2 + (hl)) * 128 + (row)) * KSTRIDE + (k))
#define SB_BASE (4 * TILE_BF16)
#define GEMM_SMEM_BYTES (8 * TILE_BF16 * 2)   // 81920

__device__ __forceinline__ void mma_bf16(float* d, const unsigned* a, const unsigned* b) {
    asm volatile(
        "mma.sync.aligned.m16n8k16.row.col.f32.bf16.bf16.f32 "
        "{%0,%1,%2,%3}, {%4,%5,%6,%7}, {%8,%9}, {%0,%1,%2,%3};"
        : "+f"(d[0]), "+f"(d[1]), "+f"(d[2]), "+f"(d[3])
        : "r"(a[0]), "r"(a[1]), "r"(a[2]), "r"(a[3]), "r"(b[0]), "r"(b[1]));
}

__device__ __forceinline__ void ldsm4(unsigned addr, unsigned& r0, unsigned& r1,
                                      unsigned& r2, unsigned& r3) {
    asm volatile("ldmatrix.sync.aligned.m8n8.x4.shared.b16 {%0,%1,%2,%3}, [%4];"
                 : "=r"(r0), "=r"(r1), "=r"(r2), "=r"(r3) : "r"(addr));
}

__device__ __forceinline__ void cvt_store(__nv_bfloat16* sm, int hiIdx, int loIdx, float4 f) {
    __nv_bfloat162 h0 = __floats2bfloat162_rn(f.x, f.y);
    __nv_bfloat162 h1 = __floats2bfloat162_rn(f.z, f.w);
    float rx = f.x - __bfloat162float(h0.x);
    float ry = f.y - __bfloat162float(h0.y);
    float rz = f.z - __bfloat162float(h1.x);
    float rw = f.w - __bfloat162float(h1.y);
    __nv_bfloat162 l0 = __floats2bfloat162_rn(rx, ry);
    __nv_bfloat162 l1 = __floats2bfloat162_rn(rz, rw);
    uint2 hv, lv;
    hv.x = *(unsigned*)&h0; hv.y = *(unsigned*)&h1;
    lv.x = *(unsigned*)&l0; lv.y = *(unsigned*)&l1;
    *(uint2*)(sm + hiIdx) = hv;
    *(uint2*)(sm + loIdx) = lv;
}

template <int EPI>
__global__ __launch_bounds__(256) void gemm_bf16x3(
    const float* __restrict__ A, const float* __restrict__ W,
    const float* __restrict__ bias, const float* __restrict__ extra,
    float* __restrict__ C, int M, int N, int Kd,
    long sA, long sW, long sC) {

    A += (long)blockIdx.z * sA;
    W += (long)blockIdx.z * sW;
    C += (long)blockIdx.z * sC;

    extern __shared__ __nv_bfloat16 sm[];

    const int tid  = threadIdx.x;
    const int lane = tid & 31;
    const int wid  = tid >> 5;
    const int wr   = wid & 3;          // 4 warp rows -> 32 rows each
    const int wc   = wid >> 2;         // 2 warp cols -> 64 cols each
    const int g    = lane >> 2;
    const int tig  = lane & 3;
    const int bm   = blockIdx.y * 128;
    const int bn   = blockIdx.x * 128;

    float acc[2][8][4];
    #pragma unroll
    for (int mi = 0; mi < 2; mi++)
        #pragma unroll
        for (int ni = 0; ni < 8; ni++)
            #pragma unroll
            for (int r = 0; r < 4; r++) acc[mi][ni][r] = 0.f;

    // loader mapping: 256 threads -> 128 rows x 2 halves; each thread 4 float4
    const int ldRow  = tid >> 1;
    const int f4base = (tid & 1) * 4;
    const int aRow   = bm + ldRow;
    const int aRowC  = (aRow < M) ? aRow : (M - 1);
    const float* aBase = A + (long)aRowC * Kd;
    const float* bBase = W + (long)(bn + ldRow) * Kd;

    // ldmatrix lane-address offsets (element units within a plane)
    const unsigned smBase = (unsigned)__cvta_generic_to_shared(sm);
    // A tiles order: (m0-7,k0-7)(m8-15,k0-7)(m0-7,k8-15)(m8-15,k8-15)
    const int aRowL = wr * 32 + (lane & 7) + ((lane >> 3) & 1) * 8;
    const int aKL   = ((lane >> 4) & 1) * 8;
    const unsigned aLaneOff = (unsigned)(aRowL * KSTRIDE + aKL);
    // B tiles order per call j: (n0,k0-7)(n0,k8-15)(n1,k0-7)(n1,k8-15), nX = j*2+X
    const int bRowL = wc * 64 + (lane & 7) + ((lane >> 4) & 1) * 8;
    const int bKL   = ((lane >> 3) & 1) * 8;
    const unsigned bLaneOff = (unsigned)(bRowL * KSTRIDE + bKL);

    const int nIter = Kd >> 5;         // 32-k chunks
    float4 fa[4], fb[4];

    // prologue: load + convert/store stage 0
    {
        const float4* ap = (const float4*)aBase;
        const float4* bp = (const float4*)bBase;
        #pragma unroll
        for (int c = 0; c < 4; c++) { fa[c] = ap[f4base + c]; fb[c] = bp[f4base + c]; }
        #pragma unroll
        for (int c = 0; c < 4; c++) {
            int kp = (f4base + c) * 4;
            cvt_store(sm, SMA(0, 0, ldRow, kp), SMA(0, 1, ldRow, kp), fa[c]);
            cvt_store(sm, SB_BASE + SMA(0, 0, ldRow, kp), SB_BASE + SMA(0, 1, ldRow, kp), fb[c]);
        }
    }

    for (int it = 0; it < nIter; ++it) {
        const int s = it & 1;
        __syncthreads();

        if (it + 1 < nIter) {
            const float4* ap = (const float4*)(aBase + (it + 1) * 32);
            const float4* bp = (const float4*)(bBase + (it + 1) * 32);
            #pragma unroll
            for (int c = 0; c < 4; c++) { fa[c] = ap[f4base + c]; fb[c] = bp[f4base + c]; }
        }

        #pragma unroll
        for (int ks = 0; ks < 2; ks++) {
            const int kb = ks * 16;
            unsigned Ah[2][4], Al[2][4], Bh[8][2], Bl[8][2];
            // plane bases (element units)
            const unsigned pA_hi = (unsigned)((s * 2 + 0) * TILE_BF16);
            const unsigned pA_lo = (unsigned)((s * 2 + 1) * TILE_BF16);
            const unsigned pB_hi = (unsigned)(SB_BASE + (s * 2 + 0) * TILE_BF16);
            const unsigned pB_lo = (unsigned)(SB_BASE + (s * 2 + 1) * TILE_BF16);
            #pragma unroll
            for (int mi = 0; mi < 2; mi++) {
                unsigned off = (unsigned)(mi * 16 * KSTRIDE + kb) + aLaneOff;
                ldsm4(smBase + 2u * (pA_hi + off), Ah[mi][0], Ah[mi][1], Ah[mi][2], Ah[mi][3]);
                ldsm4(smBase + 2u * (pA_lo + off), Al[mi][0], Al[mi][1], Al[mi][2], Al[mi][3]);
            }
            #pragma unroll
            for (int j = 0; j < 4; j++) {
                unsigned off = (unsigned)(j * 16 * KSTRIDE + kb) + bLaneOff;
                ldsm4(smBase + 2u * (pB_hi + off),
                      Bh[j * 2][0], Bh[j * 2][1], Bh[j * 2 + 1][0], Bh[j * 2 + 1][1]);
                ldsm4(smBase + 2u * (pB_lo + off),
                      Bl[j * 2][0], Bl[j * 2][1], Bl[j * 2 + 1][0], Bl[j * 2 + 1][1]);
            }
            #pragma unroll
            for (int mi = 0; mi < 2; mi++)
                #pragma unroll
                for (int ni = 0; ni < 8; ni++) {
                    mma_bf16(acc[mi][ni], Ah[mi], Bh[ni]);
                    mma_bf16(acc[mi][ni], Al[mi], Bh[ni]);
                    mma_bf16(acc[mi][ni], Ah[mi], Bl[ni]);
                }
        }

        if (it + 1 < nIter) {
            const int sn = 1 - s;
            #pragma unroll
            for (int c = 0; c < 4; c++) {
                int kp = (f4base + c) * 4;
                cvt_store(sm, SMA(sn, 0, ldRow, kp), SMA(sn, 1, ldRow, kp), fa[c]);
                cvt_store(sm, SB_BASE + SMA(sn, 0, ldRow, kp), SB_BASE + SMA(sn, 1, ldRow, kp), fb[c]);
            }
        }
    }

    // epilogue
    #pragma unroll
    for (int mi = 0; mi < 2; mi++) {
        #pragma unroll
        for (int rr = 0; rr < 2; rr++) {
            const int m = bm + wr * 32 + mi * 16 + g + rr * 8;
            if (m >= M) continue;
            #pragma unroll
            for (int ni = 0; ni < 8; ni++) {
                #pragma unroll
                for (int cc = 0; cc < 2; cc++) {
                    const int n = bn + wc * 64 + ni * 8 + tig * 2 + cc;
                    float v = acc[mi][ni][rr * 2 + cc];
                    if (EPI == EPI_BIAS) {
                        v += bias[n];
                    } else if (EPI == EPI_BIAS_RESID) {
                        v += bias[n] + extra[(long)m * N + n];
                    } else if (EPI == EPI_BIAS_GELU) {
                        v += bias[n];
                        v = 0.5f * v * (1.0f + erff(v * 0.70710678118654752f));
                    } else if (EPI == EPI_SCORES) {
                        v += extra[(long)m * N + n];
                        if (m == n) v = -1e9f;
                    }
                    C[(long)m * N + n] = v;
                }
            }
        }
    }
}

// ---------------------------------------------------------------------------
// Top-K=32 + log-softmax routing weights (clipped)
// ---------------------------------------------------------------------------
__global__ void topk_kernel(const float* __restrict__ scores,
                            int* __restrict__ routes,
                            float* __restrict__ logw) {
    __shared__ float s[1024];
    __shared__ float selv[32];
    __shared__ int   seli[32];
    __shared__ float rv[8];
    __shared__ int   ri[8];
    int row = blockIdx.x, tid = threadIdx.x;
    int lane = tid & 31, wid = tid >> 5;
    const float* src = scores + (size_t)row * 1024;
    s[tid] = src[tid]; s[tid + 256] = src[tid + 256];
    s[tid + 512] = src[tid + 512]; s[tid + 768] = src[tid + 768];
    __syncthreads();

    for (int it = 0; it < 32; it++) {
        float bv = -3.4e38f; int bi = 0x7fffffff;
        #pragma unroll
        for (int c = 0; c < 4; c++) {
            int idx = tid + c * 256;
            float v = s[idx];
            if (v > bv || (v == bv && idx < bi)) { bv = v; bi = idx; }
        }
        #pragma unroll
        for (int o = 16; o; o >>= 1) {
            float ov = __shfl_xor_sync(0xffffffffu, bv, o);
            int   oi = __shfl_xor_sync(0xffffffffu, bi, o);
            if (ov > bv || (ov == bv && oi < bi)) { bv = ov; bi = oi; }
        }
        if (lane == 0) { rv[wid] = bv; ri[wid] = bi; }
        __syncthreads();
        if (tid == 0) {
            float fv = rv[0]; int fi = ri[0];
            #pragma unroll
            for (int wn = 1; wn < 8; wn++)
                if (rv[wn] > fv || (rv[wn] == fv && ri[wn] < fi)) { fv = rv[wn]; fi = ri[wn]; }
            selv[it] = fv; seli[it] = fi;
            s[fi] = -3.4e38f;
        }
        __syncthreads();
    }

    if (tid < 32) {
        float t = selv[tid] * INV_TEMP;
        float tmax = selv[0] * INV_TEMP;
        float e = expf(t - tmax);
        float z = e;
        #pragma unroll
        for (int o = 16; o; o >>= 1) z += __shfl_xor_sync(0xffffffffu, z, o);
        float lw = t - (tmax + logf(z));
        routes[(size_t)row * 32 + tid] = seli[tid];
        logw[(size_t)row * 32 + tid] = fmaxf(lw, -10.f);
    }
}

// ---------------------------------------------------------------------------
// CLS attention
// ---------------------------------------------------------------------------
__global__ void cls_attn_kernel(const float* __restrict__ qkv,
                                float* __restrict__ attn) {
    __shared__ float q[64];
    __shared__ float sp[SS];
    __shared__ float red[32];
    __shared__ float po[4][64];
    int bh = blockIdx.x, b = bh >> 4, h = bh & 15;
    int tid = threadIdx.x;
    const float* base = qkv + (size_t)b * SS * 3072;
    if (tid < 64) q[tid] = base[h * 64 + tid];
    __syncthreads();

    float lmax = -3.4e38f;
    for (int j = tid; j < SS; j += 256) {
        const float* kr = base + (size_t)j * 3072 + 1024 + h * 64;
        float d = 0.f;
        #pragma unroll
        for (int dd = 0; dd < 64; dd++) d += q[dd] * kr[dd];
        d *= SCALE_;
        sp[j] = d;
        lmax = fmaxf(lmax, d);
    }
    float M = blockReduceMax(lmax, red);
    float ls = 0.f;
    for (int j = tid; j < SS; j += 256) {
        float e = expf(sp[j] - M);
        sp[j] = e;
        ls += e;
    }
    float Z = blockReduceSum(ls, red);

    int g = tid >> 6, d = tid & 63;
    float o = 0.f;
    for (int j = g; j < SS; j += 4)
        o += sp[j] * base[(size_t)j * 3072 + 2048 + h * 64 + d];
    po[g][d] = o;
    __syncthreads();
    if (tid < 64) {
        float r = (po[0][tid] + po[1][tid] + po[2][tid] + po[3][tid]) / Z;
        attn[(size_t)b * SS * 1024 + h * 64 + tid] = r;
    }
}

// ---------------------------------------------------------------------------
// Routed patch attention
// ---------------------------------------------------------------------------
__global__ void patch_attn_kernel(const float* __restrict__ qkv,
                                  const int* __restrict__ routes,
                                  const float* __restrict__ logw,
                                  float* __restrict__ attn) {
    __shared__ float Kg[32][64];
    __shared__ float Vg[32][64];
    __shared__ float q[64];
    __shared__ float sc[32];
    __shared__ int   rt[32];
    __shared__ float lw[32];
    __shared__ float po[4][64];
    int bp = blockIdx.x, b = bp >> 10, p = bp & 1023;
    int tid = threadIdx.x, lane = tid & 31, w = tid >> 5;
    if (tid < 32) {
        rt[tid] = routes[(size_t)bp * 32 + tid];
        lw[tid] = logw[(size_t)bp * 32 + tid];
    }
    __syncthreads();
    const float* base = qkv + (size_t)b * SS * 3072;
    const size_t qoff = (size_t)(p + 1) * 3072;

    for (int h = 0; h < HH_; h++) {
        if (tid < 64) q[tid] = base[qoff + h * 64 + tid];
        for (int e = tid; e < 2048; e += 256) {
            int k = e >> 6, d = e & 63;
            size_t toff = (size_t)(rt[k] + 1) * 3072 + h * 64 + d;
            Kg[k][d] = base[toff + 1024];
            Vg[k][d] = base[toff + 2048];
        }
        __syncthreads();

        for (int kk = w; kk < 32; kk += 8) {
            float part = q[lane] * Kg[kk][lane] + q[lane + 32] * Kg[kk][lane + 32];
            #pragma unroll
            for (int o = 16; o; o >>= 1) part += __shfl_xor_sync(0xffffffffu, part, o);
            if (lane == 0) sc[kk] = part * SCALE_ + lw[kk];
        }
        __syncthreads();

        if (tid < 32) {
            float v = sc[tid], m = v;
            #pragma unroll
            for (int o = 16; o; o >>= 1) m = fmaxf(m, __shfl_xor_sync(0xffffffffu, m, o));
            float e = expf(v - m), z = e;
            #pragma unroll
            for (int o = 16; o; o >>= 1) z += __shfl_xor_sync(0xffffffffu, z, o);
            sc[tid] = e / z;
        }
        __syncthreads();

        int g = tid >> 6, d = tid & 63;
        float o = 0.f;
        #pragma unroll
        for (int kk = g; kk < 32; kk += 4) o += sc[kk] * Vg[kk][d];
        po[g][d] = o;
        __syncthreads();
        if (tid < 64)
            attn[((size_t)b * SS + p + 1) * 1024 + h * 64 + tid] =
                po[0][tid] + po[1][tid] + po[2][tid] + po[3][tid];
        __syncthreads();
    }
}

// ---------------------------------------------------------------------------
// Orchestration
// ---------------------------------------------------------------------------
extern "C" void kernel_launch(void* const* d_in, const int* in_sizes, int n_in,
                              void* d_out, int out_size) {
    const float* x        = (const float*)d_in[0];
    const float* n1w      = (const float*)d_in[1];
    const float* n1b      = (const float*)d_in[2];
    const float* rq_w     = (const float*)d_in[3];
    const float* rq_b     = (const float*)d_in[4];
    const float* rk_w     = (const float*)d_in[5];
    const float* rk_b     = (const float*)d_in[6];
    const float* pos_bias = (const float*)d_in[7];
    const float* qkv_w    = (const float*)d_in[8];
    const float* qkv_b    = (const float*)d_in[9];
    const float* proj_w   = (const float*)d_in[10];
    const float* proj_b   = (const float*)d_in[11];
    const float* n2w      = (const float*)d_in[12];
    const float* n2b      = (const float*)d_in[13];
    const float* fc1_w    = (const float*)d_in[14];
    const float* fc1_b    = (const float*)d_in[15];
    const float* fc2_w    = (const float*)d_in[16];
    const float* fc2_b    = (const float*)d_in[17];
    float* out = (float*)d_out;

    void* sp = nullptr;
    cudaGetSymbolAddress(&sp, g_scratch);
    float* SCR = (float*)sp;
    float* XN  = SCR + OFF_XN;
    float* QR  = SCR + OFF_QR;
    float* KRb = SCR + OFF_KR;
    float* SC  = SCR + OFF_SC;
    float* QKV = SCR + OFF_QKV;
    float* ATT = SCR + OFF_ATT;
    float* HHp = SCR + OFF_HH;
    float* HN  = SCR + OFF_HN;
    float* LW  = SCR + OFF_LW;
    int*   RT  = (int*)(SCR + OFF_RT);

    cudaFuncSetAttribute(gemm_bf16x3<EPI_BIAS>,
                         cudaFuncAttributeMaxDynamicSharedMemorySize, GEMM_SMEM_BYTES);
    cudaFuncSetAttribute(gemm_bf16x3<EPI_BIAS_RESID>,
                         cudaFuncAttributeMaxDynamicSharedMemorySize, GEMM_SMEM_BYTES);
    cudaFuncSetAttribute(gemm_bf16x3<EPI_BIAS_GELU>,
                         cudaFuncAttributeMaxDynamicSharedMemorySize, GEMM_SMEM_BYTES);
    cudaFuncSetAttribute(gemm_bf16x3<EPI_SCORES>,
                         cudaFuncAttributeMaxDynamicSharedMemorySize, GEMM_SMEM_BYTES);

    // 1. LayerNorm 1
    layernorm_kernel<<<BB * SS, 256>>>(x, n1w, n1b, XN);

    // 2. Routing projections (per batch via z-stride)
    dim3 gR(8, 8, 2);
    gemm_bf16x3<EPI_BIAS><<<gR, 256, GEMM_SMEM_BYTES>>>(
        XN + 1024, rq_w, rq_b, nullptr, QR,
        1024, 1024, 1024, (long)SS * DD, 0, (long)PP * DD);
    gemm_bf16x3<EPI_BIAS><<<gR, 256, GEMM_SMEM_BYTES>>>(
        XN + 1024, rk_w, rk_b, nullptr, KRb,
        1024, 1024, 1024, (long)SS * DD, 0, (long)PP * DD);

    // 3. L2 normalize q_r and k_r
    l2norm_kernel<<<2 * BB * PP, 256>>>(QR);

    // 4. Routing scores
    gemm_bf16x3<EPI_SCORES><<<gR, 256, GEMM_SMEM_BYTES>>>(
        QR, KRb, nullptr, pos_bias, SC,
        1024, 1024, 1024, (long)PP * DD, (long)PP * DD, (long)PP * PP);

    // 5. Top-32 + routing weights
    topk_kernel<<<BB * PP, 256>>>(SC, RT, LW);

    // 6. QKV projection
    dim3 gQ(24, 17, 1);
    gemm_bf16x3<EPI_BIAS><<<gQ, 256, GEMM_SMEM_BYTES>>>(
        XN, qkv_w, qkv_b, nullptr, QKV, 2050, 3072, 1024, 0, 0, 0);

    // 7. CLS attention
    cls_attn_kernel<<<BB * HH_, 256>>>(QKV, ATT);

    // 8. Routed patch attention
    patch_attn_kernel<<<BB * PP, 256>>>(QKV, RT, LW, ATT);

    // 9. Output projection + residual
    dim3 gP(8, 17, 1);
    gemm_bf16x3<EPI_BIAS_RESID><<<gP, 256, GEMM_SMEM_BYTES>>>(
        ATT, proj_w, proj_b, x, out, 2050, 1024, 1024, 0, 0, 0);

    // 10. LayerNorm 2
    layernorm_kernel<<<BB * SS, 256>>>(out, n2w, n2b, HN);

    // 11. FC1 + exact GELU
    dim3 gF1(32, 17, 1);
    gemm_bf16x3<EPI_BIAS_GELU><<<gF1, 256, GEMM_SMEM_BYTES>>>(
        HN, fc1_w, fc1_b, nullptr, HHp, 2050, 4096, 1024, 0, 0, 0);

    // 12. FC2 + residual
    dim3 gF2(8, 17, 1);
    gemm_bf16x3<EPI_BIAS_RESID><<<gF2, 256, GEMM_SMEM_BYTES>>>(
        HHp, fc2_w, fc2_b, out, out, 2050, 1024, 4096, 0, 0, 0);

    (void)in_sizes; (void)n_in; (void)out_size;
}